// round 11
// baseline (speedup 1.0000x reference)
#include <cuda_runtime.h>
#include <math.h>

// Problem constants
#define BN    64
#define HW    784           // 28*28
#define CN    512
#define SA    28            // argmax hw splits (HWPA = 28)
#define HWPA  28
#define SB    7             // apply hw splits  (HWPB = 112)
#define HWPB  112
#define CHUNK 28            // hw per staged tile
#define NCH   4             // HWPB / CHUNK
#define WARPS 8             // warps per apply block (256 threads)
#define PAD   29            // smem row pitch (odd -> conflict-free)

// Scratch (device globals: allocation-free)
__device__ float g_pval[BN * SA * CN];
__device__ int   g_pidx[BN * SA * CN];
__device__ int   g_idx [BN * CN];

// ---------------------------------------------------------------------------
// Kernel 1: partial argmax (proven 5x: ~19.5-20us, DRAM ~66%). Unchanged.
// ---------------------------------------------------------------------------
__global__ void __launch_bounds__(CN)
argmax_partial_kernel(const float* __restrict__ x) {
    const int s = blockIdx.x;
    const int b = blockIdx.y;
    const int c = threadIdx.x;
    const int hw0 = s * HWPA;

    const size_t base = ((size_t)b * HW + hw0) * CN + c;

    float best = -INFINITY;
    int   bidx = hw0;

    #pragma unroll
    for (int i = 0; i < HWPA; ++i) {
        float v = x[base + (size_t)i * CN];
        if (v > best) {            // strict > + ascending i => first occurrence
            best = v;
            bidx = hw0 + i;
        }
    }

    const int o = (b * SA + s) * CN + c;
    g_pval[o] = best;
    g_pidx[o] = bidx;
}

// ---------------------------------------------------------------------------
// Kernel 2: combine 28 partials once per (b,c) -> g_idx (131 KB, ~2.5us).
// Ascending p <=> ascending hw + strict > => first occurrence (jnp.argmax).
// ---------------------------------------------------------------------------
__global__ void __launch_bounds__(256)
combine_kernel() {
    const int tid = blockIdx.x * 256 + threadIdx.x;   // 0 .. 32767
    const int b = tid >> 9;
    const int c = tid & 511;

    const size_t o0 = (size_t)b * SA * CN + c;
    float best = -INFINITY;
    int   idx  = 0;
    #pragma unroll
    for (int p = 0; p < SA; ++p) {
        float v = g_pval[o0 + (size_t)p * CN];
        if (v > best) { best = v; idx = g_pidx[o0 + (size_t)p * CN]; }
    }
    g_idx[tid] = idx;
}

// ---------------------------------------------------------------------------
// Kernel 3: apply with WARP-COOPERATIVE template staging.
// Block = 256 threads = 8 warps; warp owns 32 channels; grid (64,7,2) = 896
// blocks -> one wave at 7 CTAs/SM.
// Per 28-hw chunk, each warp:
//   stage:   32 coalesced 112B row-slice loads (idx broadcast via shfl)
//            into its private smem tile [32][29] (conflict-free pad)
//   compute: 28 coalesced x loads * smem template -> coalesced stores
// Only __syncwarp between phases -> warps overlap each other's staging
// latency (no block-wide serialization, unlike R5/R9).
// ---------------------------------------------------------------------------
__global__ void __launch_bounds__(256, 7)
apply_kernel(const float* __restrict__ x,
             const float* __restrict__ tp,
             float* __restrict__ out) {
    __shared__ float st[WARPS * 32 * PAD];       // 29696 B -> 7 CTAs/SM

    const int b    = blockIdx.x;
    const int s    = blockIdx.y;
    const int ct   = blockIdx.z;                 // channel half: 0 or 1
    const int w    = threadIdx.x >> 5;
    const int lane = threadIdx.x & 31;
    const int c    = ct * 256 + threadIdx.x;     // this thread's channel

    const int idx = g_idx[b * CN + c];           // coalesced; L2-hot table

    float* __restrict__ stw = st + w * 32 * PAD; // warp-private tile
    const size_t tb     = (size_t)b * HW;
    const int    hwbase = s * HWPB;
    const size_t xbase  = ((size_t)b * HW + hwbase) * CN + c;

    #pragma unroll
    for (int ch = 0; ch < NCH; ++ch) {
        const int hwc = hwbase + ch * CHUNK;

        // ---- stage: row r = warp channel r; coalesced 112B slice loads ----
        #pragma unroll 8
        for (int r = 0; r < 32; ++r) {
            const int rowIdx = __shfl_sync(0xffffffffu, idx, r);
            if (lane < CHUNK)
                stw[r * PAD + lane] = tp[(tb + (size_t)rowIdx) * HW + hwc + lane];
        }
        __syncwarp();

        // ---- compute: coalesced x/out along c; smem reads conflict-free ----
        const size_t o0 = xbase + (size_t)(ch * CHUNK) * CN;
        const float* __restrict__ tc = stw + lane * PAD;

        #pragma unroll 4
        for (int i = 0; i < CHUNK; ++i) {
            float xv = x[o0 + (size_t)i * CN];
            out[o0 + (size_t)i * CN] = fmaxf(xv * tc[i], 0.0f);
        }
        __syncwarp();                            // WAR: tile reused next chunk
    }
}

// ---------------------------------------------------------------------------
// Launch: inputs [x, t_p]; output fp32 [64,28,28,512]. Graph-capturable.
// ---------------------------------------------------------------------------
extern "C" void kernel_launch(void* const* d_in, const int* in_sizes, int n_in,
                              void* d_out, int out_size) {
    (void)in_sizes; (void)n_in; (void)out_size;
    const float* x   = (const float*)d_in[0];
    const float* tp  = (const float*)d_in[1];
    float*       out = (float*)d_out;

    dim3 gridA(SA, BN);
    argmax_partial_kernel<<<gridA, CN>>>(x);

    combine_kernel<<<128, 256>>>();

    dim3 gridB(BN, SB, 2);
    apply_kernel<<<gridB, 256>>>(x, tp, out);
}

// round 12
// speedup vs baseline: 1.2994x; 1.2994x over previous
#include <cuda_runtime.h>
#include <math.h>

// Problem constants
#define BN    64
#define HW    784           // 28*28
#define CN    512
#define SA    28            // argmax hw splits (HWPA = 28)
#define HWPA  28
#define SB    7             // apply hw splits  (HWPB = 112; 448B ≡ 0 mod 16)
#define HWPB  112
#define HWPB4 28            // HWPB / 4

// Scratch (device globals: allocation-free)
__device__ float g_pval[BN * SA * CN];
__device__ int   g_pidx[BN * SA * CN];
__device__ int   g_idx [BN * CN];

// ---------------------------------------------------------------------------
// Kernel 1: partial argmax (proven 6x: ~19.5-20us, DRAM ~66%). Unchanged.
// ---------------------------------------------------------------------------
__global__ void __launch_bounds__(CN)
argmax_partial_kernel(const float* __restrict__ x) {
    const int s = blockIdx.x;
    const int b = blockIdx.y;
    const int c = threadIdx.x;
    const int hw0 = s * HWPA;

    const size_t base = ((size_t)b * HW + hw0) * CN + c;

    float best = -INFINITY;
    int   bidx = hw0;

    #pragma unroll
    for (int i = 0; i < HWPA; ++i) {
        float v = x[base + (size_t)i * CN];
        if (v > best) {            // strict > + ascending i => first occurrence
            best = v;
            bidx = hw0 + i;
        }
    }

    const int o = (b * SA + s) * CN + c;
    g_pval[o] = best;
    g_pidx[o] = bidx;
}

// ---------------------------------------------------------------------------
// Kernel 2: combine 28 partials once per (b,c) -> g_idx (131 KB, ~2.5us).
// Ascending p <=> ascending hw + strict > => first occurrence (jnp.argmax).
// ---------------------------------------------------------------------------
__global__ void __launch_bounds__(256)
combine_kernel() {
    const int tid = blockIdx.x * 256 + threadIdx.x;   // 0 .. 32767
    const int b = tid >> 9;
    const int c = tid & 511;

    const size_t o0 = (size_t)b * SA * CN + c;
    float best = -INFINITY;
    int   idx  = 0;
    #pragma unroll
    for (int p = 0; p < SA; ++p) {
        float v = g_pval[o0 + (size_t)p * CN];
        if (v > best) { best = v; idx = g_pidx[o0 + (size_t)p * CN]; }
    }
    g_idx[tid] = idx;
}

// ---------------------------------------------------------------------------
// Kernel 3: apply — the proven per-thread-streaming shape, with the template
// stream SOFTWARE-PIPELINED: iteration j issues the (divergent, ~600ns) load
// for group j+1 BEFORE group j's coalesced x-loads/stores, so the gather
// latency overlaps a full group of streaming work instead of sitting on the
// store's critical path. unroll 2 keeps the pipeline in registers without
// blowing occupancy.
// ---------------------------------------------------------------------------
__global__ void __launch_bounds__(512)
apply_kernel(const float* __restrict__ x,
             const float* __restrict__ tp,
             float* __restrict__ out) {
    const int b = blockIdx.x;
    const int s = blockIdx.y;
    const int c = threadIdx.x;

    const int idx = g_idx[b * CN + c];    // 131 KB table, L2-hot, coalesced

    // Selected template row slice: t_p[b, idx, s*112 .. s*112+111]
    const float4* __restrict__ trow4 =
        (const float4*)(tp + ((size_t)b * HW + (size_t)idx) * HW + s * HWPB);

    const size_t base = ((size_t)b * HW + (size_t)s * HWPB) * CN + c;

    float4 t4 = __ldg(trow4);             // prime the pipeline

    #pragma unroll 2
    for (int j = 0; j < HWPB4; ++j) {
        // issue next template load first (last redundant load is an L1 hit)
        const int jn = (j + 1 < HWPB4) ? (j + 1) : (HWPB4 - 1);
        float4 t4n = __ldg(trow4 + jn);

        const size_t o = base + (size_t)(4 * j) * CN;
        float x0 = x[o];
        float x1 = x[o + (size_t)CN];
        float x2 = x[o + (size_t)(2 * CN)];
        float x3 = x[o + (size_t)(3 * CN)];

        out[o]                    = fmaxf(x0 * t4.x, 0.0f);
        out[o + (size_t)CN]       = fmaxf(x1 * t4.y, 0.0f);
        out[o + (size_t)(2 * CN)] = fmaxf(x2 * t4.z, 0.0f);
        out[o + (size_t)(3 * CN)] = fmaxf(x3 * t4.w, 0.0f);

        t4 = t4n;
    }
}

// ---------------------------------------------------------------------------
// Launch: inputs [x, t_p]; output fp32 [64,28,28,512]. Graph-capturable.
// ---------------------------------------------------------------------------
extern "C" void kernel_launch(void* const* d_in, const int* in_sizes, int n_in,
                              void* d_out, int out_size) {
    (void)in_sizes; (void)n_in; (void)out_size;
    const float* x   = (const float*)d_in[0];
    const float* tp  = (const float*)d_in[1];
    float*       out = (float*)d_out;

    dim3 gridA(SA, BN);
    argmax_partial_kernel<<<gridA, CN>>>(x);

    combine_kernel<<<128, 256>>>();

    dim3 gridB(BN, SB);
    apply_kernel<<<gridB, CN>>>(x, tp, out);
}

// round 13
// speedup vs baseline: 1.3283x; 1.0222x over previous
#include <cuda_runtime.h>
#include <math.h>

// Problem constants
#define BN    64
#define HW    784           // 28*28
#define CN    512
#define SA    28            // argmax hw splits (HWPA = 28)
#define HWPA  28
#define SB    7             // apply hw splits  (HWPB = 112; 448B ≡ 0 mod 16)
#define HWPB  112
#define HWPB4 28            // HWPB / 4
#define X_BYTES ((size_t)BN * HW * CN * sizeof(float))   // 102,760,448

// Scratch (device globals: allocation-free)
__device__ float g_pval[BN * SA * CN];
__device__ int   g_pidx[BN * SA * CN];
__device__ int   g_idx [BN * CN];

// ---------------------------------------------------------------------------
// Kernel 1: partial argmax (proven 7x: ~19.5-20us, DRAM ~66%). Unchanged.
// ---------------------------------------------------------------------------
__global__ void __launch_bounds__(CN)
argmax_partial_kernel(const float* __restrict__ x) {
    const int s = blockIdx.x;
    const int b = blockIdx.y;
    const int c = threadIdx.x;
    const int hw0 = s * HWPA;

    const size_t base = ((size_t)b * HW + hw0) * CN + c;

    float best = -INFINITY;
    int   bidx = hw0;

    #pragma unroll
    for (int i = 0; i < HWPA; ++i) {
        float v = x[base + (size_t)i * CN];
        if (v > best) {            // strict > + ascending i => first occurrence
            best = v;
            bidx = hw0 + i;
        }
    }

    const int o = (b * SA + s) * CN + c;
    g_pval[o] = best;
    g_pidx[o] = bidx;
}

// ---------------------------------------------------------------------------
// Kernel 2: combine 28 partials once per (b,c) -> g_idx (131 KB, ~2.5us).
// Ascending p <=> ascending hw + strict > => first occurrence (jnp.argmax).
// ---------------------------------------------------------------------------
__global__ void __launch_bounds__(256)
combine_kernel() {
    const int tid = blockIdx.x * 256 + threadIdx.x;   // 0 .. 32767
    const int b = tid >> 9;
    const int c = tid & 511;

    const size_t o0 = (size_t)b * SA * CN + c;
    float best = -INFINITY;
    int   idx  = 0;
    #pragma unroll
    for (int p = 0; p < SA; ++p) {
        float v = g_pval[o0 + (size_t)p * CN];
        if (v > best) { best = v; idx = g_pidx[o0 + (size_t)p * CN]; }
    }
    g_idx[tid] = idx;
}

// ---------------------------------------------------------------------------
// Kernel 3: apply — proven per-thread-streaming shape (unroll 4, __ldg
// templates, PLAIN x loads so x can hit the persisting-L2 window), with
// __stcs on out only: the write-once output stream is marked evict-first
// so it does not flush x/templates from L2. (R8's loss came from ALSO
// marking x evict-first via __ldcs — the opposite of what's needed.)
// ---------------------------------------------------------------------------
__global__ void __launch_bounds__(CN)
apply_kernel(const float* __restrict__ x,
             const float* __restrict__ tp,
             float* __restrict__ out) {
    const int b = blockIdx.x;
    const int s = blockIdx.y;
    const int c = threadIdx.x;

    const int idx = g_idx[b * CN + c];    // 131 KB table, L2-hot, coalesced

    // Selected template row slice: t_p[b, idx, s*112 .. s*112+111]
    const float4* __restrict__ trow4 =
        (const float4*)(tp + ((size_t)b * HW + (size_t)idx) * HW + s * HWPB);

    const size_t base = ((size_t)b * HW + (size_t)s * HWPB) * CN + c;

    #pragma unroll 4
    for (int j = 0; j < HWPB4; ++j) {
        const float4 t4 = __ldg(trow4 + j);
        const size_t o  = base + (size_t)(4 * j) * CN;

        float x0 = x[o];
        float x1 = x[o + (size_t)CN];
        float x2 = x[o + (size_t)(2 * CN)];
        float x3 = x[o + (size_t)(3 * CN)];

        __stcs(out + o,                    fmaxf(x0 * t4.x, 0.0f));
        __stcs(out + o + (size_t)CN,       fmaxf(x1 * t4.y, 0.0f));
        __stcs(out + o + (size_t)(2 * CN), fmaxf(x2 * t4.z, 0.0f));
        __stcs(out + o + (size_t)(3 * CN), fmaxf(x3 * t4.w, 0.0f));
    }
}

// ---------------------------------------------------------------------------
// Launch. The x tensor gets an L2 access-policy window (Persisting) on both
// big kernels so it survives the argmax->apply boundary (and graph replays)
// in L2 instead of being re-fetched from DRAM. Window size is clamped to the
// device limit; if the limit is 0 the attribute is skipped (no-op, no error).
// cudaLaunchKernelEx + launch attributes are graph-capturable.
// ---------------------------------------------------------------------------
extern "C" void kernel_launch(void* const* d_in, const int* in_sizes, int n_in,
                              void* d_out, int out_size) {
    (void)in_sizes; (void)n_in; (void)out_size;
    const float* x   = (const float*)d_in[0];
    const float* tp  = (const float*)d_in[1];
    float*       out = (float*)d_out;

    // Query (host-side, capture-safe, deterministic) the max window size.
    int dev = 0;
    cudaGetDevice(&dev);
    int max_win = 0;
    cudaDeviceGetAttribute(&max_win, cudaDevAttrMaxAccessPolicyWindowSize, dev);

    cudaLaunchAttribute attrs[1];
    int nattrs = 0;
    if (max_win > 0) {
        size_t win = X_BYTES < (size_t)max_win ? X_BYTES : (size_t)max_win;
        attrs[0].id = cudaLaunchAttributeAccessPolicyWindow;
        attrs[0].val.accessPolicyWindow.base_ptr  = (void*)x;
        attrs[0].val.accessPolicyWindow.num_bytes = win;
        attrs[0].val.accessPolicyWindow.hitRatio  = 1.0f;
        attrs[0].val.accessPolicyWindow.hitProp   = cudaAccessPropertyPersisting;
        attrs[0].val.accessPolicyWindow.missProp  = cudaAccessPropertyStreaming;
        nattrs = 1;
    }

    // Kernel 1: argmax partials (window: x lines marked persisting as read)
    cudaLaunchConfig_t cfgA = {};
    cfgA.gridDim  = dim3(SA, BN);
    cfgA.blockDim = dim3(CN);
    cfgA.attrs    = attrs;
    cfgA.numAttrs = nattrs;
    cudaLaunchKernelEx(&cfgA, argmax_partial_kernel, x);

    // Kernel 2: combine (tiny; no window needed)
    combine_kernel<<<128, 256>>>();

    // Kernel 3: apply (window: x reads hit persisting lines)
    cudaLaunchConfig_t cfgB = {};
    cfgB.gridDim  = dim3(BN, SB);
    cfgB.blockDim = dim3(CN);
    cfgB.attrs    = attrs;
    cfgB.numAttrs = nattrs;
    cudaLaunchKernelEx(&cfgB, apply_kernel, x, tp, out);
}